// round 1
// baseline (speedup 1.0000x reference)
#include <cuda_runtime.h>
#include <cuda_bf16.h>

// Problem constants
#define Bn   16
#define CIN  64
#define COUT 64
#define KK   3
#define Hdim 128
#define Wdim 128
#define HE   8

// Conv tiling
#define TW 32     // tile width  (16 pixel-pairs)
#define TH 16     // tile height
#define COG 16    // channels-out per block (4 groups)
#define XPITCH 35 // smem row pitch (34 cols used) -> conflict-free
#define XS_FLOATS (64 * 18 * XPITCH)      // 40320
#define WS_FLOATS (64 * 9 * 16)           // 9216
#define SMEM_BYTES ((XS_FLOATS + WS_FLOATS) * 4)

// Scratch (static device globals; no runtime allocation)
__device__ float g_k3[Bn * 32 * 9];                    // [b][c][tap]
__device__ float g_w[Bn * 4 * 64 * 9 * 16];            // [b][cog][ci][tap][co16]

__device__ __forceinline__ float lrelu(float v) { return v > 0.f ? v : 0.01f * v; }

__device__ __forceinline__ void fma2(unsigned long long& acc, unsigned long long a,
                                     unsigned long long b) {
    asm("fma.rn.f32x2 %0, %1, %2, %0;" : "+l"(acc) : "l"(a), "l"(b));
}
__device__ __forceinline__ unsigned long long pack2(float lo, float hi) {
    unsigned long long r;
    asm("mov.b64 %0, {%1, %2};" : "=l"(r) : "f"(lo), "f"(hi));
    return r;
}
__device__ __forceinline__ void unpack2(unsigned long long v, float& lo, float& hi) {
    asm("mov.b64 {%0, %1}, %2;" : "=f"(lo), "=f"(hi) : "l"(v));
}

// ---------------------------------------------------------------------------
// Kernel A: hypernet stages 1-3 -> g_k3[b][c(32)][tap(9)]
// ---------------------------------------------------------------------------
__global__ void knet_kernel(const float* __restrict__ h,
                            const float* __restrict__ fc_w,
                            const float* __restrict__ fc_b,
                            const float* __restrict__ w1, const float* __restrict__ b1,
                            const float* __restrict__ w2, const float* __restrict__ b2) {
    __shared__ float k1[Bn * 144];   // [b][c(16)*9+t]
    __shared__ float k2[Bn * 288];   // [b][c(32)*9+t]
    int tid = threadIdx.x;

    for (int i = tid; i < Bn * 144; i += 256) {
        int b = i / 144, j = i % 144;
        float s = fc_b[j];
#pragma unroll
        for (int q = 0; q < HE; q++) s += h[b * HE + q] * fc_w[j * HE + q];
        k1[i] = lrelu(s);
    }
    __syncthreads();

    for (int i = tid; i < Bn * 288; i += 256) {
        int b = i / 288, r = i % 288;
        int o = r / 9, t = r % 9;
        float s = b1[o];
#pragma unroll
        for (int c = 0; c < 16; c++) s += w1[o * 16 + c] * k1[b * 144 + c * 9 + t];
        k2[i] = lrelu(s);
    }
    __syncthreads();

    for (int i = tid; i < Bn * 288; i += 256) {
        int b = i / 288, r = i % 288;
        int o = r / 9, t = r % 9;
        float s = b2[o];
#pragma unroll
        for (int c = 0; c < 32; c++) s += w2[o * 32 + c] * k2[b * 288 + c * 9 + t];
        g_k3[i] = lrelu(s);
    }
}

// ---------------------------------------------------------------------------
// Kernel B: stage 4 -> g_w[b][cog][ci][tap][co16]
// grid: (co=64, b=16), 256 threads
// ---------------------------------------------------------------------------
__global__ void wgen_kernel(const float* __restrict__ w3,
                            const float* __restrict__ b3) {
    int co = blockIdx.x;
    int b  = blockIdx.y;
    __shared__ float k3s[288];        // [c(32)][t(9)]
    __shared__ float w3s[64 * 32];    // rows co*64 .. co*64+63
    int tid = threadIdx.x;

    for (int i = tid; i < 288; i += 256) k3s[i] = g_k3[b * 288 + i];
    for (int i = tid; i < 2048; i += 256) w3s[i] = w3[(co * 64) * 32 + i];
    __syncthreads();

    int cog = co >> 4, col = co & 15;
    for (int e = tid; e < 576; e += 256) {
        int ci = e / 9, t = e % 9;
        float s = b3[co * 64 + ci];
#pragma unroll
        for (int c = 0; c < 32; c++) s += w3s[ci * 32 + c] * k3s[c * 9 + t];
        g_w[((((b * 4 + cog) * 64 + ci) * 9 + t) << 4) + col] = s;
    }
}

// ---------------------------------------------------------------------------
// Kernel C: the conv. grid (32 tiles, 4 co-groups, 16 batch), 256 threads.
// Each thread: 2 horizontal pixels x 16 co, f32x2 packed FMA (co-pairs in halves).
// ---------------------------------------------------------------------------
__global__ void __launch_bounds__(256, 1)
conv_kernel(const float* __restrict__ x, const float* __restrict__ bias,
            float* __restrict__ y) {
    int tile = blockIdx.x;            // 0..31 : 4 across x, 8 down y
    int cog  = blockIdx.y;            // 0..3
    int b    = blockIdx.z;            // 0..15
    int tx0 = (tile & 3) * TW;
    int ty0 = (tile >> 2) * TH;

    extern __shared__ float smem[];
    float* xs = smem;                  // [64][18][XPITCH]
    float* ws = smem + XS_FLOATS;      // [64][9][16]

    const float* xb = x + ((size_t)b * CIN) * (Hdim * Wdim);
    int tid = threadIdx.x;

    // ---- load x tile (with zero halo) ----
    for (int i = tid; i < 64 * 18 * 34; i += 256) {
        int ci = i / (18 * 34);
        int rr = (i / 34) % 18;
        int cc = i % 34;
        int gy = ty0 - 1 + rr;
        int gx = tx0 - 1 + cc;
        float v = 0.f;
        if ((unsigned)gy < (unsigned)Hdim && (unsigned)gx < (unsigned)Wdim)
            v = xb[ci * (Hdim * Wdim) + gy * Wdim + gx];
        xs[ci * (18 * XPITCH) + rr * XPITCH + cc] = v;
    }
    // ---- load weights (already in [ci][tap][co16] order) ----
    const float* wg = g_w + (size_t)((b * 4 + cog) * 64) * 144;
    for (int i = tid; i < WS_FLOATS; i += 256) ws[i] = wg[i];
    __syncthreads();

    int p   = tid & 15;    // pixel pair index (px0 = 2p, px1 = 2p+1)
    int row = tid >> 4;    // 0..15

    unsigned long long acc[16];
#pragma unroll
    for (int i = 0; i < 16; i++) acc[i] = 0ULL;

    const float* xrow = xs + row * XPITCH + 2 * p;

    for (int ci = 0; ci < 64; ci++) {
        const float* xp = xrow + ci * (18 * XPITCH);
        float xv[3][4];
#pragma unroll
        for (int r3 = 0; r3 < 3; r3++)
#pragma unroll
            for (int c4 = 0; c4 < 4; c4++) xv[r3][c4] = xp[r3 * XPITCH + c4];

        unsigned long long xd[3][4];
#pragma unroll
        for (int r3 = 0; r3 < 3; r3++)
#pragma unroll
            for (int c4 = 0; c4 < 4; c4++) xd[r3][c4] = pack2(xv[r3][c4], xv[r3][c4]);

        const float* wp = ws + ci * 144;
#pragma unroll
        for (int kr = 0; kr < 3; kr++) {
#pragma unroll
            for (int kc = 0; kc < 3; kc++) {
                const ulonglong2* wq =
                    reinterpret_cast<const ulonglong2*>(wp + (kr * 3 + kc) * 16);
                unsigned long long x0 = xd[kr][kc];      // px0 duplicated
                unsigned long long x1 = xd[kr][kc + 1];  // px1 duplicated
#pragma unroll
                for (int q = 0; q < 4; q++) {
                    ulonglong2 wv = wq[q];               // co pairs (4q,4q+1),(4q+2,4q+3)
                    fma2(acc[(2 * q + 0) * 2 + 0], x0, wv.x);
                    fma2(acc[(2 * q + 0) * 2 + 1], x1, wv.x);
                    fma2(acc[(2 * q + 1) * 2 + 0], x0, wv.y);
                    fma2(acc[(2 * q + 1) * 2 + 1], x1, wv.y);
                }
            }
        }
    }

    // ---- epilogue: add bias, write float2 per (co, pixel-pair) ----
    int gx = tx0 + 2 * p;
    int gy = ty0 + row;
    float* yb = y + (((size_t)b * COUT + cog * COG)) * (Hdim * Wdim) + gy * Wdim + gx;
#pragma unroll
    for (int j = 0; j < 8; j++) {
        float c0p0, c1p0, c0p1, c1p1;
        unpack2(acc[j * 2 + 0], c0p0, c1p0);
        unpack2(acc[j * 2 + 1], c0p1, c1p1);
        float bi0 = bias[cog * COG + 2 * j];
        float bi1 = bias[cog * COG + 2 * j + 1];
        float2 o0 = make_float2(c0p0 + bi0, c0p1 + bi0);
        float2 o1 = make_float2(c1p0 + bi1, c1p1 + bi1);
        *reinterpret_cast<float2*>(yb + (size_t)(2 * j) * (Hdim * Wdim))     = o0;
        *reinterpret_cast<float2*>(yb + (size_t)(2 * j + 1) * (Hdim * Wdim)) = o1;
    }
}

// ---------------------------------------------------------------------------
extern "C" void kernel_launch(void* const* d_in, const int* in_sizes, int n_in,
                              void* d_out, int out_size) {
    const float* x    = (const float*)d_in[0];
    const float* h    = (const float*)d_in[1];
    const float* fc_w = (const float*)d_in[2];
    const float* fc_b = (const float*)d_in[3];
    const float* w1   = (const float*)d_in[4];
    const float* b1   = (const float*)d_in[5];
    const float* w2   = (const float*)d_in[6];
    const float* b2   = (const float*)d_in[7];
    const float* w3   = (const float*)d_in[8];
    const float* b3   = (const float*)d_in[9];
    const float* bias = (const float*)d_in[10];
    float* y = (float*)d_out;

    cudaFuncSetAttribute(conv_kernel, cudaFuncAttributeMaxDynamicSharedMemorySize,
                         SMEM_BYTES);

    knet_kernel<<<1, 256>>>(h, fc_w, fc_b, w1, b1, w2, b2);
    wgen_kernel<<<dim3(64, 16), 256>>>(w3, b3);
    conv_kernel<<<dim3(32, 4, 16), 256, SMEM_BYTES>>>(x, bias, y);
}

// round 2
// speedup vs baseline: 1.3422x; 1.3422x over previous
#include <cuda_runtime.h>
#include <cuda_bf16.h>

// Problem constants
#define Bn   16
#define CIN  64
#define COUT 64
#define Hdim 128
#define Wdim 128
#define HE   8

// Conv tiling: 32x32 pixel tile, 16 co per block, 4 px x 16 co per thread
#define TW 32
#define TH 32
#define CHUNK 16                    // ci per smem stage (4 stages)
#define XPITCH 35                   // 34 used cols, odd pitch -> conflict-free
#define XS_CH (CHUNK * 34 * XPITCH) // 19040 floats
#define WS_CH (CHUNK * 9 * 16)      // 2304 floats
#define SMEM_BYTES ((XS_CH + WS_CH) * 4)  // 85376 B -> 2 CTAs/SM

// Scratch (static device globals; no runtime allocation)
__device__ float g_k3[Bn * 32 * 9];                    // [b][c][tap]
__device__ float g_w[Bn * 4 * 64 * 9 * 16];            // [b][cog][ci][tap][co16]

__device__ __forceinline__ float lrelu(float v) { return v > 0.f ? v : 0.01f * v; }

__device__ __forceinline__ void fma2(unsigned long long& acc, unsigned long long a,
                                     unsigned long long b) {
    asm("fma.rn.f32x2 %0, %1, %2, %0;" : "+l"(acc) : "l"(a), "l"(b));
}
__device__ __forceinline__ unsigned long long pack2(float lo, float hi) {
    unsigned long long r;
    asm("mov.b64 %0, {%1, %2};" : "=l"(r) : "f"(lo), "f"(hi));
    return r;
}
__device__ __forceinline__ void unpack2(unsigned long long v, float& lo, float& hi) {
    asm("mov.b64 {%0, %1}, %2;" : "=f"(lo), "=f"(hi) : "l"(v));
}

// ---------------------------------------------------------------------------
// Kernel A: hypernet stages 1-3 -> g_k3[b][c(32)][tap(9)].  One block per b.
// ---------------------------------------------------------------------------
__global__ void knet_kernel(const float* __restrict__ h,
                            const float* __restrict__ fc_w,
                            const float* __restrict__ fc_b,
                            const float* __restrict__ w1, const float* __restrict__ b1,
                            const float* __restrict__ w2, const float* __restrict__ b2) {
    int b = blockIdx.x;
    __shared__ float k1[144];
    __shared__ float k2[288];
    int tid = threadIdx.x;

    if (tid < 144) {
        float s = fc_b[tid];
#pragma unroll
        for (int q = 0; q < HE; q++) s += h[b * HE + q] * fc_w[tid * HE + q];
        k1[tid] = lrelu(s);
    }
    __syncthreads();

    if (tid < 288) {
        int o = tid / 9, t = tid % 9;
        float s = b1[o];
#pragma unroll
        for (int c = 0; c < 16; c++) s += w1[o * 16 + c] * k1[c * 9 + t];
        k2[tid] = lrelu(s);
    }
    __syncthreads();

    if (tid < 288) {
        int o = tid / 9, t = tid % 9;
        float s = b2[o];
#pragma unroll
        for (int c = 0; c < 32; c++) s += w2[o * 32 + c] * k2[c * 9 + t];
        g_k3[b * 288 + tid] = lrelu(s);
    }
}

// ---------------------------------------------------------------------------
// Kernel B: stage 4 -> g_w[b][cog][ci][tap][co16]
// grid: (co=64, b=16), 256 threads
// ---------------------------------------------------------------------------
__global__ void wgen_kernel(const float* __restrict__ w3,
                            const float* __restrict__ b3) {
    int co = blockIdx.x;
    int b  = blockIdx.y;
    __shared__ float k3s[288];        // [c(32)][t(9)]
    __shared__ float w3s[64 * 32];    // rows co*64 .. co*64+63
    int tid = threadIdx.x;

    for (int i = tid; i < 288; i += 256) k3s[i] = g_k3[b * 288 + i];
    for (int i = tid; i < 2048; i += 256) w3s[i] = w3[(co * 64) * 32 + i];
    __syncthreads();

    int cog = co >> 4, col = co & 15;
    for (int e = tid; e < 576; e += 256) {
        int ci = e / 9, t = e % 9;
        float s = b3[co * 64 + ci];
#pragma unroll
        for (int c = 0; c < 32; c++) s += w3s[ci * 32 + c] * k3s[c * 9 + t];
        g_w[((((b * 4 + cog) * 64 + ci) * 9 + t) << 4) + col] = s;
    }
}

// ---------------------------------------------------------------------------
// Kernel C: conv. grid (16 tiles, 4 cog, 16 b), 256 threads, 2 CTAs/SM.
// Thread = 4 horizontal pixels x 16 co; co-pairs packed in f32x2 halves.
// ci streamed through smem in chunks of 16.
// ---------------------------------------------------------------------------
__global__ void __launch_bounds__(256, 2)
conv_kernel(const float* __restrict__ x, const float* __restrict__ bias,
            float* __restrict__ y) {
    int tile = blockIdx.x;            // 0..15 : 4 across x, 4 down y
    int cog  = blockIdx.y;            // 0..3
    int b    = blockIdx.z;            // 0..15
    int tx0 = (tile & 3) * TW;
    int ty0 = (tile >> 2) * TH;

    extern __shared__ float smem[];
    float* xs = smem;                  // [CHUNK][34][XPITCH]
    float* ws = smem + XS_CH;          // [CHUNK][9][16]

    const float* xb = x + ((size_t)b * CIN) * (Hdim * Wdim);
    const float* wg = g_w + (size_t)((b * 4 + cog) * 64) * 144;
    int tid = threadIdx.x;

    int p   = tid & 7;    // pixel quad index: px = 4p..4p+3
    int row = tid >> 3;   // 0..31

    unsigned long long acc[8][4];
#pragma unroll
    for (int i = 0; i < 8; i++)
#pragma unroll
        for (int j = 0; j < 4; j++) acc[i][j] = 0ULL;

    for (int ch = 0; ch < CIN / CHUNK; ch++) {
        // ---- load x chunk (with zero halo) ----
        for (int i = tid; i < CHUNK * 34 * 34; i += 256) {
            int ci = i / (34 * 34);
            int rr = (i / 34) % 34;
            int cc = i % 34;
            int gy = ty0 - 1 + rr;
            int gx = tx0 - 1 + cc;
            float v = 0.f;
            if ((unsigned)gy < (unsigned)Hdim && (unsigned)gx < (unsigned)Wdim)
                v = xb[(ch * CHUNK + ci) * (Hdim * Wdim) + gy * Wdim + gx];
            xs[ci * (34 * XPITCH) + rr * XPITCH + cc] = v;
        }
        // ---- load weight chunk ----
        for (int i = tid; i < WS_CH; i += 256) ws[i] = wg[ch * WS_CH + i];
        __syncthreads();

        for (int ci = 0; ci < CHUNK; ci++) {
            const float* xp = xs + ci * (34 * XPITCH) + row * XPITCH + 4 * p;
            float xv[3][6];
#pragma unroll
            for (int r3 = 0; r3 < 3; r3++)
#pragma unroll
                for (int c6 = 0; c6 < 6; c6++) xv[r3][c6] = xp[r3 * XPITCH + c6];

            const float* wp = ws + ci * 144;
#pragma unroll
            for (int kr = 0; kr < 3; kr++) {
                unsigned long long xd[6];
#pragma unroll
                for (int c6 = 0; c6 < 6; c6++) xd[c6] = pack2(xv[kr][c6], xv[kr][c6]);
#pragma unroll
                for (int kc = 0; kc < 3; kc++) {
                    const ulonglong2* wq =
                        reinterpret_cast<const ulonglong2*>(wp + (kr * 3 + kc) * 16);
#pragma unroll
                    for (int q = 0; q < 4; q++) {
                        ulonglong2 wv = wq[q];           // co (4q,4q+1),(4q+2,4q+3)
#pragma unroll
                        for (int j = 0; j < 4; j++) {
                            fma2(acc[2 * q + 0][j], xd[kc + j], wv.x);
                            fma2(acc[2 * q + 1][j], xd[kc + j], wv.y);
                        }
                    }
                }
            }
        }
        __syncthreads();
    }

    // ---- epilogue: add bias, one STG.128 (4 px) per co ----
    int gx = tx0 + 4 * p;
    int gy = ty0 + row;
    float* yb = y + ((size_t)b * COUT + cog * 16) * (Hdim * Wdim) + gy * Wdim + gx;
#pragma unroll
    for (int pr = 0; pr < 8; pr++) {
        float bi0 = bias[cog * 16 + 2 * pr];
        float bi1 = bias[cog * 16 + 2 * pr + 1];
        float lo[4], hi[4];
#pragma unroll
        for (int j = 0; j < 4; j++) unpack2(acc[pr][j], lo[j], hi[j]);
        float4 o0 = make_float4(lo[0] + bi0, lo[1] + bi0, lo[2] + bi0, lo[3] + bi0);
        float4 o1 = make_float4(hi[0] + bi1, hi[1] + bi1, hi[2] + bi1, hi[3] + bi1);
        *reinterpret_cast<float4*>(yb + (size_t)(2 * pr) * (Hdim * Wdim))     = o0;
        *reinterpret_cast<float4*>(yb + (size_t)(2 * pr + 1) * (Hdim * Wdim)) = o1;
    }
}

// ---------------------------------------------------------------------------
extern "C" void kernel_launch(void* const* d_in, const int* in_sizes, int n_in,
                              void* d_out, int out_size) {
    const float* x    = (const float*)d_in[0];
    const float* h    = (const float*)d_in[1];
    const float* fc_w = (const float*)d_in[2];
    const float* fc_b = (const float*)d_in[3];
    const float* w1   = (const float*)d_in[4];
    const float* b1   = (const float*)d_in[5];
    const float* w2   = (const float*)d_in[6];
    const float* b2   = (const float*)d_in[7];
    const float* w3   = (const float*)d_in[8];
    const float* b3   = (const float*)d_in[9];
    const float* bias = (const float*)d_in[10];
    float* y = (float*)d_out;

    cudaFuncSetAttribute(conv_kernel, cudaFuncAttributeMaxDynamicSharedMemorySize,
                         SMEM_BYTES);

    knet_kernel<<<16, 288>>>(h, fc_w, fc_b, w1, b1, w2, b2);
    wgen_kernel<<<dim3(64, 16), 256>>>(w3, b3);
    conv_kernel<<<dim3(16, 4, 16), 256, SMEM_BYTES>>>(x, bias, y);
}